// round 5
// baseline (speedup 1.0000x reference)
#include <cuda_runtime.h>
#include <cuda_bf16.h>
#include <math.h>
#include <stdint.h>

#define BB 4
#define DD 256
#define LL 4096
#define NN (BB*LL)      // 16384 tokens
#define KK 8192
#define EPSF 1e-12f
#define MARGIN 4e-3f

#define KSPLIT 16
#define CPS (KK/KSPLIT)        // 512 codes per slice
#define NCAND (KSPLIT*3)       // 48 candidates per token

// ---- GEMM tiling (round-2 proven shape) ----
#define BM 128
#define BN 128
#define BK 32
#define LDT 56
#define TILE_HALVES (128*LDT)
#define TILE_BYTES  (TILE_HALVES*2)
#define GEMM_SMEM   (4*TILE_BYTES)   // 57344

// ---- device scratch ----
__device__ float          g_cbn[KK*DD];     // normalized codebook fp32 (8 MB)
__device__ float          g_xn[NN*DD];      // normalized tokens fp32 (16 MB)
__device__ __nv_bfloat16  g_ch[KK*DD];      // normalized codebook bf16 (4 MB)
__device__ __nv_bfloat16  g_xh[NN*DD];      // normalized tokens bf16 (8 MB)
__device__ float          g_norm[NN];
__device__ float          g_candv[NN*NCAND];
__device__ int            g_candi[NN*NCAND];
__device__ double         g_acc;

// ------------------------------------------------------------------
__global__ void init_acc_kernel() { g_acc = 0.0; }

__device__ __forceinline__ uint32_t pack_bf16x2(float lo, float hi) {
    uint32_t r;
    asm("cvt.rn.bf16x2.f32 %0, %1, %2;" : "=r"(r) : "f"(hi), "f"(lo));
    return r;
}

// one warp per codebook row: cn = c / max(||c||, eps); fp32 + bf16 outputs
__global__ void normalize_codebook_kernel(const float* __restrict__ cb) {
    int row  = blockIdx.x * 8 + (threadIdx.x >> 5);
    int lane = threadIdx.x & 31;
    const float4* src = (const float4*)(cb + (size_t)row * DD);
    float4 v0 = src[lane];
    float4 v1 = src[lane + 32];
    float ss = v0.x*v0.x + v0.y*v0.y + v0.z*v0.z + v0.w*v0.w
             + v1.x*v1.x + v1.y*v1.y + v1.z*v1.z + v1.w*v1.w;
    #pragma unroll
    for (int o = 16; o; o >>= 1) ss += __shfl_xor_sync(~0u, ss, o);
    float inv = 1.0f / fmaxf(sqrtf(ss), EPSF);
    v0.x*=inv; v0.y*=inv; v0.z*=inv; v0.w*=inv;
    v1.x*=inv; v1.y*=inv; v1.z*=inv; v1.w*=inv;
    float4* dst = (float4*)(g_cbn + (size_t)row * DD);
    dst[lane] = v0; dst[lane + 32] = v1;
    uint2* hd = (uint2*)(g_ch + (size_t)row * DD);
    hd[lane]      = make_uint2(pack_bf16x2(v0.x, v0.y), pack_bf16x2(v0.z, v0.w));
    hd[lane + 32] = make_uint2(pack_bf16x2(v1.x, v1.y), pack_bf16x2(v1.z, v1.w));
}

// fused: transpose [B,D,L] tile -> norms -> xn fp32 + bf16 (single x read)
__global__ void make_xn_kernel(const float* __restrict__ x) {
    __shared__ float tile[32][261];
    int b = blockIdx.y, l0 = blockIdx.x * 32;
    int tid = threadIdx.x, wid = tid >> 5, lane = tid & 31;
    #pragma unroll
    for (int j = 0; j < 32; j++) {
        int d = wid * 32 + j;
        tile[lane][d] = x[(size_t)b * DD * LL + (size_t)d * LL + l0 + lane];
    }
    __syncthreads();
    #pragma unroll
    for (int i = 0; i < 4; i++) {
        int t = wid * 4 + i;
        int n = b * LL + l0 + t;
        float ss = 0.0f;
        #pragma unroll
        for (int j = 0; j < 8; j++) { float v = tile[t][lane + 32*j]; ss = fmaf(v, v, ss); }
        #pragma unroll
        for (int o = 16; o; o >>= 1) ss += __shfl_xor_sync(~0u, ss, o);
        float nrm = fmaxf(sqrtf(ss), EPSF);
        float inv = 1.0f / nrm;
        if (lane == 0) g_norm[n] = nrm;
        #pragma unroll
        for (int j = 0; j < 8; j++) {
            int d = lane + 32*j;
            float v = tile[t][d] * inv;
            g_xn[(size_t)n * DD + d] = v;
            g_xh[(size_t)n * DD + d] = __float2bfloat16(v);
        }
    }
}

// ------------------------------------------------------------------
#define CP_ASYNC16(dst, src) \
    asm volatile("cp.async.cg.shared.global [%0], [%1], 16;\n" :: "r"(dst), "l"(src))

__device__ __forceinline__ void load_tile(int kt, int buf, uint32_t smem_u32,
                                          const __nv_bfloat16* A,
                                          const __nv_bfloat16* B, int tid) {
    #pragma unroll
    for (int i = 0; i < 2; i++) {
        int idx = tid + i * 256;
        int row = idx >> 2;
        int kc  = (idx & 3) * 8;
        uint32_t dA = smem_u32 + buf * (2*TILE_BYTES) + (row * LDT + kc) * 2;
        CP_ASYNC16(dA, A + (size_t)row * DD + kt * BK + kc);
        uint32_t dB = dA + TILE_BYTES;
        CP_ASYNC16(dB, B + (size_t)row * DD + kt * BK + kc);
    }
}

// fused bf16 mma.sync GEMM + per-(token,slice) top-3.
// grid = (KSPLIT, NN/BM); CTA = 128 tokens x 512 codes (4 chunks of 128).
__global__ void __launch_bounds__(256, 2) gemm_topk_kernel() {
    extern __shared__ __nv_bfloat16 sm[];
    uint32_t smem_u32 = (uint32_t)__cvta_generic_to_shared(sm);
    int tid = threadIdx.x;
    int wid = tid >> 5, lane = tid & 31;
    int warp_m = wid & 3, warp_n = wid >> 2;     // 4x2 warps: 32 rows x 64 cols
    int grp = lane >> 2, qid = lane & 3;
    int slice = blockIdx.x;
    int mbase = blockIdx.y * BM;
    const __nv_bfloat16* Ag = g_xh + (size_t)mbase * DD;
    const __nv_bfloat16* Bg = g_ch + (size_t)slice * CPS * DD;

    // per-thread top-3 for each of 4 row-slots
    float v1[4], v2[4], v3[4]; int i1[4], i2[4], i3[4];
    #pragma unroll
    for (int s = 0; s < 4; s++) {
        v1[s] = v2[s] = v3[s] = -3.0f;
        i1[s] = i2[s] = i3[s] = 0x7fffffff;
    }

    #pragma unroll 1
    for (int kc = 0; kc < CPS / BN; kc++) {
        const __nv_bfloat16* Bc = Bg + (size_t)kc * BN * DD;

        float c[2][8][4];
        #pragma unroll
        for (int mi = 0; mi < 2; mi++)
            #pragma unroll
            for (int ni = 0; ni < 8; ni++)
                #pragma unroll
                for (int j = 0; j < 4; j++) c[mi][ni][j] = 0.0f;

        load_tile(0, 0, smem_u32, Ag, Bc, tid);
        asm volatile("cp.async.commit_group;\n" ::);

        #pragma unroll 1
        for (int kt = 0; kt < DD / BK; kt++) {
            if (kt < DD / BK - 1) {
                load_tile(kt + 1, (kt + 1) & 1, smem_u32, Ag, Bc, tid);
                asm volatile("cp.async.commit_group;\n" ::);
                asm volatile("cp.async.wait_group 1;\n" ::);
            } else {
                asm volatile("cp.async.wait_group 0;\n" ::);
            }
            __syncthreads();

            const __nv_bfloat16* sA = sm + (kt & 1) * (2 * TILE_HALVES);
            const __nv_bfloat16* sB = sA + TILE_HALVES;
            #pragma unroll
            for (int ks = 0; ks < BK; ks += 16) {
                uint32_t a[2][4], b[8][2];
                #pragma unroll
                for (int mi = 0; mi < 2; mi++) {
                    const __nv_bfloat16* pa = sA + (warp_m*32 + mi*16 + grp) * LDT + ks + qid*2;
                    a[mi][0] = *(const uint32_t*)(pa);
                    a[mi][1] = *(const uint32_t*)(pa + 8*LDT);
                    a[mi][2] = *(const uint32_t*)(pa + 8);
                    a[mi][3] = *(const uint32_t*)(pa + 8*LDT + 8);
                }
                #pragma unroll
                for (int ni = 0; ni < 8; ni++) {
                    const __nv_bfloat16* pb = sB + (warp_n*64 + ni*8 + grp) * LDT + ks + qid*2;
                    b[ni][0] = *(const uint32_t*)(pb);
                    b[ni][1] = *(const uint32_t*)(pb + 8);
                }
                #pragma unroll
                for (int mi = 0; mi < 2; mi++)
                    #pragma unroll
                    for (int ni = 0; ni < 8; ni++)
                        asm volatile(
                            "mma.sync.aligned.m16n8k16.row.col.f32.bf16.bf16.f32 "
                            "{%0,%1,%2,%3}, {%4,%5,%6,%7}, {%8,%9}, {%0,%1,%2,%3};\n"
                            : "+f"(c[mi][ni][0]), "+f"(c[mi][ni][1]),
                              "+f"(c[mi][ni][2]), "+f"(c[mi][ni][3])
                            : "r"(a[mi][0]), "r"(a[mi][1]), "r"(a[mi][2]), "r"(a[mi][3]),
                              "r"(b[ni][0]), "r"(b[ni][1]));
            }
            __syncthreads();
        }

        // chunk epilogue: running top-3 per row-slot (fast-path guarded)
        int cbase = slice * CPS + kc * BN + warp_n * 64 + qid * 2;
        #pragma unroll
        for (int s = 0; s < 4; s++) {
            int mi = s >> 1, h = s & 1;
            float m0 = -3.0f;
            #pragma unroll
            for (int ni = 0; ni < 8; ni++)
                m0 = fmaxf(m0, fmaxf(c[mi][ni][h*2], c[mi][ni][h*2+1]));
            if (m0 > v3[s]) {
                #pragma unroll
                for (int ni = 0; ni < 8; ni++)
                    #pragma unroll
                    for (int j = 0; j < 2; j++) {
                        float v = c[mi][ni][h*2 + j];
                        int col = cbase + ni*8 + j;
                        if (v > v1[s]) {
                            v3[s]=v2[s]; i3[s]=i2[s];
                            v2[s]=v1[s]; i2[s]=i1[s];
                            v1[s]=v;     i1[s]=col;
                        } else if (v > v2[s]) {
                            v3[s]=v2[s]; i3[s]=i2[s];
                            v2[s]=v;     i2[s]=col;
                        } else if (v > v3[s]) {
                            v3[s]=v;     i3[s]=col;
                        }
                    }
            }
        }
    }

    // intra-CTA merge: per row, 8 threads x top-3 -> slice top-3
    float* mv = (float*)sm;                 // [128][24]
    int*   mi_ = (int*)(mv + 128*24);       // [128][24]
    #pragma unroll
    for (int s = 0; s < 4; s++) {
        int row = warp_m*32 + (s>>1)*16 + (s&1)*8 + grp;
        int base = row * 24 + (warp_n*4 + qid) * 3;
        mv[base+0] = v1[s]; mi_[base+0] = i1[s];
        mv[base+1] = v2[s]; mi_[base+1] = i2[s];
        mv[base+2] = v3[s]; mi_[base+2] = i3[s];
    }
    __syncthreads();
    if (tid < 128) {
        float b1=-3.0f, b2=-3.0f, b3=-3.0f;
        int   j1=0x7fffffff, j2=0x7fffffff, j3=0x7fffffff;
        #pragma unroll
        for (int s = 0; s < 24; s++) {
            float v = mv[tid*24 + s]; int k = mi_[tid*24 + s];
            if (v > b1 || (v == b1 && k < j1)) { b3=b2;j3=j2; b2=b1;j2=j1; b1=v;j1=k; }
            else if (v > b2 || (v == b2 && k < j2)) { b3=b2;j3=j2; b2=v;j2=k; }
            else if (v > b3 || (v == b3 && k < j3)) { b3=v;j3=k; }
        }
        int n = mbase + tid;
        int base = n * NCAND + slice * 3;
        g_candv[base+0] = b1; g_candi[base+0] = j1;
        g_candv[base+1] = b2; g_candi[base+1] = j2;
        g_candv[base+2] = b3; g_candi[base+2] = j3;
    }
}

// ------------------------------------------------------------------
// fused: margin rescue over 48 candidates (exact fp32) -> rotation
// -> commit loss -> transposed write.  block = 32 tokens, warp = 4 tokens.
__global__ void rotate_out_kernel(float* __restrict__ out) {
    __shared__ float tile[256][33];
    int b = blockIdx.y, l0 = blockIdx.x * 32;
    int tid = threadIdx.x, wid = tid >> 5, lane = tid & 31;

    #pragma unroll
    for (int i = 0; i < 4; i++) {
        int t = wid * 4 + i;
        int n = b * LL + l0 + t;

        // load 48 candidates: lane holds slot lane, and slot 32+lane if lane<16
        float va = g_candv[n*NCAND + lane];
        int   ka = g_candi[n*NCAND + lane];
        float vb = (lane < 16) ? g_candv[n*NCAND + 32 + lane] : -3.0f;
        int   kb = (lane < 16) ? g_candi[n*NCAND + 32 + lane] : 0x7fffffff;
        float rmax = fmaxf(va, vb);
        #pragma unroll
        for (int o = 16; o; o >>= 1) rmax = fmaxf(rmax, __shfl_xor_sync(~0u, rmax, o));
        float thr = rmax - MARGIN;

        const float4* xp = (const float4*)(g_xn + (size_t)n * DD);
        float4 xa0 = xp[lane*2], xa1 = xp[lane*2 + 1];
        float bestv = -3.0f; int besti = 0x7fffffff;
        for (int ci = 0; ci < NCAND; ci++) {
            float v; int k;
            if (ci < 32) { v = __shfl_sync(~0u, va, ci);      k = __shfl_sync(~0u, ka, ci); }
            else         { v = __shfl_sync(~0u, vb, ci - 32); k = __shfl_sync(~0u, kb, ci - 32); }
            if (v >= thr) {
                const float4* cp = (const float4*)(g_cbn + (size_t)k * DD);
                float4 c0 = cp[lane*2], c1 = cp[lane*2 + 1];
                float d = xa0.x*c0.x + xa0.y*c0.y + xa0.z*c0.z + xa0.w*c0.w
                        + xa1.x*c1.x + xa1.y*c1.y + xa1.z*c1.z + xa1.w*c1.w;
                #pragma unroll
                for (int o = 16; o; o >>= 1) d += __shfl_xor_sync(~0u, d, o);
                if (d > bestv || (d == bestv && k < besti)) { bestv = d; besti = k; }
            }
        }

        float nrm = g_norm[n];
        const float4* qp = (const float4*)(g_cbn + (size_t)besti * DD);
        float4 x0 = xp[lane], x1 = xp[lane + 32];
        float4 q0 = qp[lane], q1 = qp[lane + 32];
        float s0x = x0.x + q0.x, s0y = x0.y + q0.y, s0z = x0.z + q0.z, s0w = x0.w + q0.w;
        float s1x = x1.x + q1.x, s1y = x1.y + q1.y, s1z = x1.z + q1.z, s1w = x1.w + q1.w;
        float ss = s0x*s0x + s0y*s0y + s0z*s0z + s0w*s0w
                 + s1x*s1x + s1y*s1y + s1z*s1z + s1w*s1w;
        float xs = x0.x*s0x + x0.y*s0y + x0.z*s0z + x0.w*s0w
                 + x1.x*s1x + x1.y*s1y + x1.z*s1z + x1.w*s1w;
        #pragma unroll
        for (int o = 16; o; o >>= 1) {
            ss += __shfl_xor_sync(~0u, ss, o);
            xs += __shfl_xor_sync(~0u, xs, o);
        }
        float sn = fmaxf(sqrtf(ss), EPSF);
        float cc = 2.0f * (xs / sn) / sn;

        float4 r0, r1;
        r0.x = x0.x - cc*s0x + 2.0f*q0.x;  r0.y = x0.y - cc*s0y + 2.0f*q0.y;
        r0.z = x0.z - cc*s0z + 2.0f*q0.z;  r0.w = x0.w - cc*s0w + 2.0f*q0.w;
        r1.x = x1.x - cc*s1x + 2.0f*q1.x;  r1.y = x1.y - cc*s1y + 2.0f*q1.y;
        r1.z = x1.z - cc*s1z + 2.0f*q1.z;  r1.w = x1.w - cc*s1w + 2.0f*q1.w;

        int d0 = lane * 4;
        tile[d0+0][t] = r0.x; tile[d0+1][t] = r0.y; tile[d0+2][t] = r0.z; tile[d0+3][t] = r0.w;
        tile[128+d0+0][t] = r1.x; tile[128+d0+1][t] = r1.y;
        tile[128+d0+2][t] = r1.z; tile[128+d0+3][t] = r1.w;

        float d0x = r0.x - x0.x*nrm, d0y = r0.y - x0.y*nrm, d0z = r0.z - x0.z*nrm, d0w = r0.w - x0.w*nrm;
        float d1x = r1.x - x1.x*nrm, d1y = r1.y - x1.y*nrm, d1z = r1.z - x1.z*nrm, d1w = r1.w - x1.w*nrm;
        float cs = d0x*d0x + d0y*d0y + d0z*d0z + d0w*d0w
                 + d1x*d1x + d1y*d1y + d1z*d1z + d1w*d1w;
        #pragma unroll
        for (int o = 16; o; o >>= 1) cs += __shfl_xor_sync(~0u, cs, o);
        if (lane == 0) atomicAdd(&g_acc, (double)cs);
    }
    __syncthreads();

    #pragma unroll
    for (int j = 0; j < 32; j++) {
        int d = wid * 32 + j;
        out[(size_t)b * DD * LL + (size_t)d * LL + l0 + lane] = tile[d][lane];
    }
}

__global__ void finalize_kernel(float* __restrict__ out, int out_size) {
    long q = (long)BB * DD * LL;
    float loss = (float)(0.25 * g_acc / (double)((long)NN * DD));
    for (long i = q + threadIdx.x; i < (long)out_size; i += blockDim.x) out[i] = loss;
}

// ------------------------------------------------------------------
extern "C" void kernel_launch(void* const* d_in, const int* in_sizes, int n_in,
                              void* d_out, int out_size) {
    const float* x  = (const float*)d_in[0];   // [4,256,4096]
    const float* cb = (const float*)d_in[1];   // [8192,256]
    float* out = (float*)d_out;

    static int attr_set = 0;
    if (!attr_set) {
        cudaFuncSetAttribute(gemm_topk_kernel,
                             cudaFuncAttributeMaxDynamicSharedMemorySize, GEMM_SMEM);
        attr_set = 1;
    }

    init_acc_kernel<<<1, 1>>>();
    normalize_codebook_kernel<<<KK / 8, 256>>>(cb);
    make_xn_kernel<<<dim3(LL / 32, BB), 256>>>(x);
    gemm_topk_kernel<<<dim3(KSPLIT, NN / BM), 256, GEMM_SMEM>>>();
    rotate_out_kernel<<<dim3(LL / 32, BB), 256>>>(out);
    finalize_kernel<<<1, 256>>>(out, out_size);
}

// round 7
// speedup vs baseline: 1.8810x; 1.8810x over previous
#include <cuda_runtime.h>
#include <cuda_bf16.h>
#include <math.h>
#include <stdint.h>

#define BB 4
#define DD 256
#define LL 4096
#define NN (BB*LL)      // 16384 tokens
#define KK 8192
#define EPSF 1e-12f
#define MARGIN 0.03f          // fp8 rescue margin (unscaled sims)
#define F8SCALE 16.0f         // per-side scale -> dots scaled by 256

#define KSPLIT 16
#define CPS (KK/KSPLIT)        // 512 codes per slice
#define NCAND (KSPLIT*3)       // 48 candidates per token

// ---- GEMM tiling ----
#define BM 128
#define BN 128
#define BKB 128                 // k-bytes per stage (128 e4m3 elems)
#define SLK 144                 // smem row stride bytes (conflict-free)
#define STAGE_B (128*SLK)       // 18432 per operand
#define STAGE_BYTES (2*STAGE_B) // 36864 (A+B)
#define NSTAGES 8               // 4 chunks x 2 k-stages
#define GSMEM (3*STAGE_BYTES)   // 110592

// ---- device scratch ----
__device__ float    g_cbn[KK*DD];     // normalized codebook fp32 (8 MB)
__device__ float    g_xn[NN*DD];      // normalized tokens fp32 (16 MB)
__device__ uint8_t  g_c8[KK*DD];      // fp8 e4m3 codebook *16 (2 MB)
__device__ uint8_t  g_x8[NN*DD];      // fp8 e4m3 tokens *16 (4 MB)
__device__ float    g_norm[NN];
__device__ float    g_candv[NN*NCAND];
__device__ int      g_candi[NN*NCAND];
__device__ double   g_acc;

// ------------------------------------------------------------------
__global__ void init_acc_kernel() { g_acc = 0.0; }

// result: low byte = e4m3(lo), high byte = e4m3(hi)
__device__ __forceinline__ uint16_t pack_e4m3x2(float lo, float hi) {
    uint16_t r;
    asm("cvt.rn.satfinite.e4m3x2.f32 %0, %1, %2;" : "=h"(r) : "f"(hi), "f"(lo));
    return r;
}

// one warp per codebook row: cn = c / max(||c||, eps); fp32 + fp8 outputs
__global__ void normalize_codebook_kernel(const float* __restrict__ cb) {
    int row  = blockIdx.x * 8 + (threadIdx.x >> 5);
    int lane = threadIdx.x & 31;
    const float4* src = (const float4*)(cb + (size_t)row * DD);
    float4 v0 = src[lane];
    float4 v1 = src[lane + 32];
    float ss = v0.x*v0.x + v0.y*v0.y + v0.z*v0.z + v0.w*v0.w
             + v1.x*v1.x + v1.y*v1.y + v1.z*v1.z + v1.w*v1.w;
    #pragma unroll
    for (int o = 16; o; o >>= 1) ss += __shfl_xor_sync(~0u, ss, o);
    float inv = 1.0f / fmaxf(sqrtf(ss), EPSF);
    v0.x*=inv; v0.y*=inv; v0.z*=inv; v0.w*=inv;
    v1.x*=inv; v1.y*=inv; v1.z*=inv; v1.w*=inv;
    float4* dst = (float4*)(g_cbn + (size_t)row * DD);
    dst[lane] = v0; dst[lane + 32] = v1;
    uint32_t u0 = (uint32_t)pack_e4m3x2(v0.x*F8SCALE, v0.y*F8SCALE)
                | ((uint32_t)pack_e4m3x2(v0.z*F8SCALE, v0.w*F8SCALE) << 16);
    uint32_t u1 = (uint32_t)pack_e4m3x2(v1.x*F8SCALE, v1.y*F8SCALE)
                | ((uint32_t)pack_e4m3x2(v1.z*F8SCALE, v1.w*F8SCALE) << 16);
    uint32_t* h8 = (uint32_t*)(g_c8 + (size_t)row * DD);
    h8[lane] = u0; h8[lane + 32] = u1;
}

// fused: transpose [B,D,L] tile -> norms -> xn fp32 + fp8 (single x read)
__global__ void make_xn_kernel(const float* __restrict__ x) {
    __shared__ float tile[32][261];
    int b = blockIdx.y, l0 = blockIdx.x * 32;
    int tid = threadIdx.x, wid = tid >> 5, lane = tid & 31;
    #pragma unroll
    for (int j = 0; j < 32; j++) {
        int d = wid * 32 + j;
        tile[lane][d] = x[(size_t)b * DD * LL + (size_t)d * LL + l0 + lane];
    }
    __syncthreads();
    #pragma unroll
    for (int i = 0; i < 4; i++) {
        int t = wid * 4 + i;
        int n = b * LL + l0 + t;
        float ss = 0.0f;
        #pragma unroll
        for (int j = 0; j < 8; j++) { float v = tile[t][lane + 32*j]; ss = fmaf(v, v, ss); }
        #pragma unroll
        for (int o = 16; o; o >>= 1) ss += __shfl_xor_sync(~0u, ss, o);
        float nrm = fmaxf(sqrtf(ss), EPSF);
        float inv = 1.0f / nrm;
        if (lane == 0) g_norm[n] = nrm;
        #pragma unroll
        for (int j = 0; j < 8; j++) {
            int d = lane + 32*j;
            float v = tile[t][d] * inv;
            g_xn[(size_t)n * DD + d] = v;
            // FIX (round-6 bug): e4m3(v*16) is the LOW byte of pack(lo=v*16, hi=0)
            g_x8[(size_t)n * DD + d] = (uint8_t)(pack_e4m3x2(v*F8SCALE, 0.0f) & 0xFF);
        }
    }
}

// ------------------------------------------------------------------
#define CP_ASYNC16(dst, src) \
    asm volatile("cp.async.cg.shared.global [%0], [%1], 16;\n" :: "r"(dst), "l"(src))

// load stage s (k-bytes [(s&1)*128, +128), chunk kc = s>>1) into buffer buf
__device__ __forceinline__ void load_stage(int s, int buf, uint32_t sb,
                                           int mbase, int slice, int tid) {
    int kb = (s & 1) * BKB;
    int kc = s >> 1;
    uint32_t dstA = sb + buf * STAGE_BYTES;
    const uint8_t* srcA = g_x8 + (size_t)mbase * DD + kb;
    const uint8_t* srcB = g_c8 + (size_t)(slice * CPS + kc * BN) * DD + kb;
    #pragma unroll
    for (int i = 0; i < 4; i++) {
        int idx = tid + i * 256;
        int row = idx >> 3, c = (idx & 7) * 16;
        CP_ASYNC16(dstA + row * SLK + c, srcA + (size_t)row * DD + c);
        CP_ASYNC16(dstA + STAGE_B + row * SLK + c, srcB + (size_t)row * DD + c);
    }
}

// fused fp8 mma GEMM + per-(token,slice) packed top-3.
// grid = (KSPLIT, NN/BM); CTA = 128 tokens x 512 codes.
__global__ void __launch_bounds__(256, 2) gemm_topk_kernel() {
    extern __shared__ uint8_t sm[];
    uint32_t sb = (uint32_t)__cvta_generic_to_shared(sm);
    int tid = threadIdx.x;
    int wid = tid >> 5, lane = tid & 31;
    int warp_m = wid & 3, warp_n = wid >> 2;     // 4x2 warps: 32 rows x 64 cols
    int grp = lane >> 2, qid = lane & 3;
    int slice = blockIdx.x;
    int mbase = blockIdx.y * BM;

    load_stage(0, 0, sb, mbase, slice, tid);
    asm volatile("cp.async.commit_group;\n" ::);
    load_stage(1, 1, sb, mbase, slice, tid);
    asm volatile("cp.async.commit_group;\n" ::);

    uint32_t t1[4], t2[4], t3[4];
    #pragma unroll
    for (int s4 = 0; s4 < 4; s4++) { t1[s4]=0; t2[s4]=0; t3[s4]=0; }

    float c[2][8][4];

    #pragma unroll 1
    for (int s = 0; s < NSTAGES; s++) {
        if ((s & 1) == 0) {
            #pragma unroll
            for (int mi = 0; mi < 2; mi++)
                #pragma unroll
                for (int ni = 0; ni < 8; ni++)
                    #pragma unroll
                    for (int j = 0; j < 4; j++) c[mi][ni][j] = 0.0f;
        }
        if (s < NSTAGES - 2) asm volatile("cp.async.wait_group 1;\n" ::);
        else                 asm volatile("cp.async.wait_group 0;\n" ::);
        __syncthreads();
        if (s + 2 < NSTAGES) {
            load_stage(s + 2, (s + 2) % 3, sb, mbase, slice, tid);
            asm volatile("cp.async.commit_group;\n" ::);
        }

        const uint8_t* sA = sm + (s % 3) * STAGE_BYTES;
        const uint8_t* sB = sA + STAGE_B;
        #pragma unroll
        for (int ks = 0; ks < 4; ks++) {
            int ksb = ks * 32;
            uint32_t a[2][4], b[8][2];
            #pragma unroll
            for (int mi = 0; mi < 2; mi++) {
                const uint8_t* pa = sA + (warp_m*32 + mi*16 + grp) * SLK + ksb + qid*4;
                a[mi][0] = *(const uint32_t*)(pa);
                a[mi][1] = *(const uint32_t*)(pa + 8*SLK);
                a[mi][2] = *(const uint32_t*)(pa + 16);
                a[mi][3] = *(const uint32_t*)(pa + 8*SLK + 16);
            }
            #pragma unroll
            for (int ni = 0; ni < 8; ni++) {
                const uint8_t* pb = sB + (warp_n*64 + ni*8 + grp) * SLK + ksb + qid*4;
                b[ni][0] = *(const uint32_t*)(pb);
                b[ni][1] = *(const uint32_t*)(pb + 16);
            }
            #pragma unroll
            for (int mi = 0; mi < 2; mi++)
                #pragma unroll
                for (int ni = 0; ni < 8; ni++)
                    asm volatile(
                        "mma.sync.aligned.m16n8k32.row.col.f32.e4m3.e4m3.f32 "
                        "{%0,%1,%2,%3}, {%4,%5,%6,%7}, {%8,%9}, {%0,%1,%2,%3};\n"
                        : "+f"(c[mi][ni][0]), "+f"(c[mi][ni][1]),
                          "+f"(c[mi][ni][2]), "+f"(c[mi][ni][3])
                        : "r"(a[mi][0]), "r"(a[mi][1]), "r"(a[mi][2]), "r"(a[mi][3]),
                          "r"(b[ni][0]), "r"(b[ni][1]));
        }

        if (s & 1) {   // chunk kc = s>>1 complete: update packed top-3
            int kc = s >> 1;
            #pragma unroll
            for (int s4 = 0; s4 < 4; s4++) {
                int mi = s4 >> 1, h = s4 & 1;
                float m0 = -1e30f;
                #pragma unroll
                for (int ni = 0; ni < 8; ni++)
                    m0 = fmaxf(m0, fmaxf(c[mi][ni][h*2], c[mi][ni][h*2+1]));
                if ((__float_as_uint(m0 + 512.0f) | 0x1FFu) >= t3[s4]) {
                    #pragma unroll
                    for (int ni = 0; ni < 8; ni++)
                        #pragma unroll
                        for (int j = 0; j < 2; j++) {
                            float v = c[mi][ni][h*2 + j];
                            uint32_t col = kc*128 + warp_n*64 + ni*8 + qid*2 + j;
                            uint32_t u = (__float_as_uint(v + 512.0f) & 0xFFFFFE00u)
                                       | (511u - col);
                            if (u > t1[s4])      { t3[s4]=t2[s4]; t2[s4]=t1[s4]; t1[s4]=u; }
                            else if (u > t2[s4]) { t3[s4]=t2[s4]; t2[s4]=u; }
                            else if (u > t3[s4]) { t3[s4]=u; }
                        }
                }
            }
        }
    }

    // intra-CTA merge: per row, 8 threads x top-3 keys -> slice top-3
    __syncthreads();
    uint32_t* mk = (uint32_t*)sm;      // [128][24]
    #pragma unroll
    for (int s4 = 0; s4 < 4; s4++) {
        int row = warp_m*32 + (s4>>1)*16 + (s4&1)*8 + grp;
        int base = row * 24 + (warp_n*4 + qid) * 3;
        mk[base+0] = t1[s4]; mk[base+1] = t2[s4]; mk[base+2] = t3[s4];
    }
    __syncthreads();
    if (tid < 128) {
        uint32_t b1=0, b2=0, b3=0;
        #pragma unroll
        for (int s2 = 0; s2 < 24; s2++) {
            uint32_t u = mk[tid*24 + s2];
            if (u > b1)      { b3=b2; b2=b1; b1=u; }
            else if (u > b2) { b3=b2; b2=u; }
            else if (u > b3) { b3=u; }
        }
        int n = mbase + tid;
        int base = n * NCAND + slice * 3;
        uint32_t ks_[3] = {b1, b2, b3};
        #pragma unroll
        for (int j = 0; j < 3; j++) {
            uint32_t u = ks_[j];
            g_candv[base+j] = (__uint_as_float(u & 0xFFFFFE00u) - 512.0f) * (1.0f/256.0f);
            g_candi[base+j] = slice * CPS + (int)(511u - (u & 0x1FFu));
        }
    }
}

// ------------------------------------------------------------------
// fused: margin rescue over 48 candidates (exact fp32) -> rotation
// -> commit loss -> transposed write.  block = 32 tokens, warp = 4 tokens.
__global__ void rotate_out_kernel(float* __restrict__ out) {
    __shared__ float tile[256][33];
    int b = blockIdx.y, l0 = blockIdx.x * 32;
    int tid = threadIdx.x, wid = tid >> 5, lane = tid & 31;

    #pragma unroll
    for (int i = 0; i < 4; i++) {
        int t = wid * 4 + i;
        int n = b * LL + l0 + t;

        float va = g_candv[n*NCAND + lane];
        int   ka = g_candi[n*NCAND + lane];
        float vb = (lane < 16) ? g_candv[n*NCAND + 32 + lane] : -3.0f;
        int   kb = (lane < 16) ? g_candi[n*NCAND + 32 + lane] : 0x7fffffff;
        float rmax = fmaxf(va, vb);
        #pragma unroll
        for (int o = 16; o; o >>= 1) rmax = fmaxf(rmax, __shfl_xor_sync(~0u, rmax, o));
        float thr = rmax - MARGIN;

        const float4* xp = (const float4*)(g_xn + (size_t)n * DD);
        float4 xa0 = xp[lane*2], xa1 = xp[lane*2 + 1];
        float bestv = -3.0f; int besti = 0x7fffffff;
        for (int ci = 0; ci < NCAND; ci++) {
            float v; int k;
            if (ci < 32) { v = __shfl_sync(~0u, va, ci);      k = __shfl_sync(~0u, ka, ci); }
            else         { v = __shfl_sync(~0u, vb, ci - 32); k = __shfl_sync(~0u, kb, ci - 32); }
            if (v >= thr) {
                const float4* cp = (const float4*)(g_cbn + (size_t)k * DD);
                float4 c0 = cp[lane*2], c1 = cp[lane*2 + 1];
                float d = xa0.x*c0.x + xa0.y*c0.y + xa0.z*c0.z + xa0.w*c0.w
                        + xa1.x*c1.x + xa1.y*c1.y + xa1.z*c1.z + xa1.w*c1.w;
                #pragma unroll
                for (int o = 16; o; o >>= 1) d += __shfl_xor_sync(~0u, d, o);
                if (d > bestv || (d == bestv && k < besti)) { bestv = d; besti = k; }
            }
        }

        float nrm = g_norm[n];
        const float4* qp = (const float4*)(g_cbn + (size_t)besti * DD);
        float4 x0 = xp[lane], x1 = xp[lane + 32];
        float4 q0 = qp[lane], q1 = qp[lane + 32];
        float s0x = x0.x + q0.x, s0y = x0.y + q0.y, s0z = x0.z + q0.z, s0w = x0.w + q0.w;
        float s1x = x1.x + q1.x, s1y = x1.y + q1.y, s1z = x1.z + q1.z, s1w = x1.w + q1.w;
        float ss = s0x*s0x + s0y*s0y + s0z*s0z + s0w*s0w
                 + s1x*s1x + s1y*s1y + s1z*s1z + s1w*s1w;
        float xs = x0.x*s0x + x0.y*s0y + x0.z*s0z + x0.w*s0w
                 + x1.x*s1x + x1.y*s1y + x1.z*s1z + x1.w*s1w;
        #pragma unroll
        for (int o = 16; o; o >>= 1) {
            ss += __shfl_xor_sync(~0u, ss, o);
            xs += __shfl_xor_sync(~0u, xs, o);
        }
        float sn = fmaxf(sqrtf(ss), EPSF);
        float cc = 2.0f * (xs / sn) / sn;

        float4 r0, r1;
        r0.x = x0.x - cc*s0x + 2.0f*q0.x;  r0.y = x0.y - cc*s0y + 2.0f*q0.y;
        r0.z = x0.z - cc*s0z + 2.0f*q0.z;  r0.w = x0.w - cc*s0w + 2.0f*q0.w;
        r1.x = x1.x - cc*s1x + 2.0f*q1.x;  r1.y = x1.y - cc*s1y + 2.0f*q1.y;
        r1.z = x1.z - cc*s1z + 2.0f*q1.z;  r1.w = x1.w - cc*s1w + 2.0f*q1.w;

        int d0 = lane * 4;
        tile[d0+0][t] = r0.x; tile[d0+1][t] = r0.y; tile[d0+2][t] = r0.z; tile[d0+3][t] = r0.w;
        tile[128+d0+0][t] = r1.x; tile[128+d0+1][t] = r1.y;
        tile[128+d0+2][t] = r1.z; tile[128+d0+3][t] = r1.w;

        float d0x = r0.x - x0.x*nrm, d0y = r0.y - x0.y*nrm, d0z = r0.z - x0.z*nrm, d0w = r0.w - x0.w*nrm;
        float d1x = r1.x - x1.x*nrm, d1y = r1.y - x1.y*nrm, d1z = r1.z - x1.z*nrm, d1w = r1.w - x1.w*nrm;
        float cs = d0x*d0x + d0y*d0y + d0z*d0z + d0w*d0w
                 + d1x*d1x + d1y*d1y + d1z*d1z + d1w*d1w;
        #pragma unroll
        for (int o = 16; o; o >>= 1) cs += __shfl_xor_sync(~0u, cs, o);
        if (lane == 0) atomicAdd(&g_acc, (double)cs);
    }
    __syncthreads();

    #pragma unroll
    for (int j = 0; j < 32; j++) {
        int d = wid * 32 + j;
        out[(size_t)b * DD * LL + (size_t)d * LL + l0 + lane] = tile[d][lane];
    }
}

__global__ void finalize_kernel(float* __restrict__ out, int out_size) {
    long q = (long)BB * DD * LL;
    float loss = (float)(0.25 * g_acc / (double)((long)NN * DD));
    for (long i = q + threadIdx.x; i < (long)out_size; i += blockDim.x) out[i] = loss;
}

// ------------------------------------------------------------------
extern "C" void kernel_launch(void* const* d_in, const int* in_sizes, int n_in,
                              void* d_out, int out_size) {
    const float* x  = (const float*)d_in[0];   // [4,256,4096]
    const float* cb = (const float*)d_in[1];   // [8192,256]
    float* out = (float*)d_out;

    static int attr_set = 0;
    if (!attr_set) {
        cudaFuncSetAttribute(gemm_topk_kernel,
                             cudaFuncAttributeMaxDynamicSharedMemorySize, GSMEM);
        attr_set = 1;
    }

    init_acc_kernel<<<1, 1>>>();
    normalize_codebook_kernel<<<KK / 8, 256>>>(cb);
    make_xn_kernel<<<dim3(LL / 32, BB), 256>>>(x);
    gemm_topk_kernel<<<dim3(KSPLIT, NN / BM), 256, GSMEM>>>();
    rotate_out_kernel<<<dim3(LL / 32, BB), 256>>>(out);
    finalize_kernel<<<1, 256>>>(out, out_size);
}

// round 8
// speedup vs baseline: 1.9738x; 1.0494x over previous
#include <cuda_runtime.h>
#include <cuda_bf16.h>
#include <math.h>
#include <stdint.h>

#define BB 4
#define DD 256
#define LL 4096
#define NN (BB*LL)      // 16384 tokens
#define KK 8192
#define EPSF 1e-12f
#define MARGIN 0.03f          // fp8 rescue margin (unscaled sims)
#define F8SCALE 16.0f         // per-side scale -> dots scaled by 256

#define KSPLIT 16
#define CPS (KK/KSPLIT)        // 512 codes per slice
#define NCAND (KSPLIT*3)       // 48 candidates per token

// ---- GEMM tiling ----
#define BM 128
#define BN 128
#define BKB 128                 // k-bytes per stage (128 e4m3 elems)
#define SLK 144                 // smem row stride bytes (conflict-free)
#define STAGE_B (128*SLK)       // 18432 per operand
#define STAGE_BYTES (2*STAGE_B) // 36864 (A+B)
#define NSTAGES 8               // 4 chunks x 2 k-stages
#define GSMEM (3*STAGE_BYTES)   // 110592

// ---- device scratch ----
__device__ float    g_cbn[KK*DD];     // normalized codebook fp32 (8 MB)
__device__ float    g_xn[NN*DD];      // normalized tokens fp32 (16 MB)
__device__ uint8_t  g_c8[KK*DD];      // fp8 e4m3 codebook *16 (2 MB)
__device__ uint8_t  g_x8[NN*DD];      // fp8 e4m3 tokens *16 (4 MB)
__device__ float    g_norm[NN];
__device__ float    g_candv[NN*NCAND];
__device__ int      g_candi[NN*NCAND];
__device__ double   g_acc;

// ------------------------------------------------------------------
__global__ void init_acc_kernel() { g_acc = 0.0; }

// result: low byte = e4m3(lo), high byte = e4m3(hi)
__device__ __forceinline__ uint16_t pack_e4m3x2(float lo, float hi) {
    uint16_t r;
    asm("cvt.rn.satfinite.e4m3x2.f32 %0, %1, %2;" : "=h"(r) : "f"(hi), "f"(lo));
    return r;
}

#define LDMATRIX_X4(r0, r1, r2, r3, addr) \
    asm volatile("ldmatrix.sync.aligned.m8n8.x4.shared.b16 {%0,%1,%2,%3}, [%4];" \
        : "=r"(r0), "=r"(r1), "=r"(r2), "=r"(r3) : "r"(addr))

// one warp per codebook row: cn = c / max(||c||, eps); fp32 + fp8 outputs
__global__ void normalize_codebook_kernel(const float* __restrict__ cb) {
    int row  = blockIdx.x * 8 + (threadIdx.x >> 5);
    int lane = threadIdx.x & 31;
    const float4* src = (const float4*)(cb + (size_t)row * DD);
    float4 v0 = src[lane];
    float4 v1 = src[lane + 32];
    float ss = v0.x*v0.x + v0.y*v0.y + v0.z*v0.z + v0.w*v0.w
             + v1.x*v1.x + v1.y*v1.y + v1.z*v1.z + v1.w*v1.w;
    #pragma unroll
    for (int o = 16; o; o >>= 1) ss += __shfl_xor_sync(~0u, ss, o);
    float inv = 1.0f / fmaxf(sqrtf(ss), EPSF);
    v0.x*=inv; v0.y*=inv; v0.z*=inv; v0.w*=inv;
    v1.x*=inv; v1.y*=inv; v1.z*=inv; v1.w*=inv;
    float4* dst = (float4*)(g_cbn + (size_t)row * DD);
    dst[lane] = v0; dst[lane + 32] = v1;
    uint32_t u0 = (uint32_t)pack_e4m3x2(v0.x*F8SCALE, v0.y*F8SCALE)
                | ((uint32_t)pack_e4m3x2(v0.z*F8SCALE, v0.w*F8SCALE) << 16);
    uint32_t u1 = (uint32_t)pack_e4m3x2(v1.x*F8SCALE, v1.y*F8SCALE)
                | ((uint32_t)pack_e4m3x2(v1.z*F8SCALE, v1.w*F8SCALE) << 16);
    uint32_t* h8 = (uint32_t*)(g_c8 + (size_t)row * DD);
    h8[lane] = u0; h8[lane + 32] = u1;
}

// fused: transpose [B,D,L] tile -> norms -> xn fp32 + fp8 (single x read)
__global__ void make_xn_kernel(const float* __restrict__ x) {
    __shared__ float tile[32][261];
    int b = blockIdx.y, l0 = blockIdx.x * 32;
    int tid = threadIdx.x, wid = tid >> 5, lane = tid & 31;
    #pragma unroll
    for (int j = 0; j < 32; j++) {
        int d = wid * 32 + j;
        tile[lane][d] = x[(size_t)b * DD * LL + (size_t)d * LL + l0 + lane];
    }
    __syncthreads();
    #pragma unroll
    for (int i = 0; i < 4; i++) {
        int t = wid * 4 + i;
        int n = b * LL + l0 + t;
        float ss = 0.0f;
        #pragma unroll
        for (int j = 0; j < 8; j++) { float v = tile[t][lane + 32*j]; ss = fmaf(v, v, ss); }
        #pragma unroll
        for (int o = 16; o; o >>= 1) ss += __shfl_xor_sync(~0u, ss, o);
        float nrm = fmaxf(sqrtf(ss), EPSF);
        float inv = 1.0f / nrm;
        if (lane == 0) g_norm[n] = nrm;
        #pragma unroll
        for (int j = 0; j < 8; j++) {
            int d = lane + 32*j;
            float v = tile[t][d] * inv;
            g_xn[(size_t)n * DD + d] = v;
            g_x8[(size_t)n * DD + d] = (uint8_t)(pack_e4m3x2(v*F8SCALE, 0.0f) & 0xFF);
        }
    }
}

// ------------------------------------------------------------------
#define CP_ASYNC16(dst, src) \
    asm volatile("cp.async.cg.shared.global [%0], [%1], 16;\n" :: "r"(dst), "l"(src))

// load stage s (k-bytes [(s&1)*128, +128), chunk kc = s>>1) into buffer buf
__device__ __forceinline__ void load_stage(int s, int buf, uint32_t sb,
                                           int mbase, int slice, int tid) {
    int kb = (s & 1) * BKB;
    int kc = s >> 1;
    uint32_t dstA = sb + buf * STAGE_BYTES;
    const uint8_t* srcA = g_x8 + (size_t)mbase * DD + kb;
    const uint8_t* srcB = g_c8 + (size_t)(slice * CPS + kc * BN) * DD + kb;
    #pragma unroll
    for (int i = 0; i < 4; i++) {
        int idx = tid + i * 256;
        int row = idx >> 3, c = (idx & 7) * 16;
        CP_ASYNC16(dstA + row * SLK + c, srcA + (size_t)row * DD + c);
        CP_ASYNC16(dstA + STAGE_B + row * SLK + c, srcB + (size_t)row * DD + c);
    }
}

// fused fp8 mma GEMM + per-(token,slice) packed top-3; ldmatrix feed.
// grid = (KSPLIT, NN/BM); CTA = 128 tokens x 512 codes.
__global__ void __launch_bounds__(256, 2) gemm_topk_kernel() {
    extern __shared__ uint8_t sm[];
    uint32_t sb = (uint32_t)__cvta_generic_to_shared(sm);
    int tid = threadIdx.x;
    int wid = tid >> 5, lane = tid & 31;
    int warp_m = wid & 3, warp_n = wid >> 2;     // 4x2 warps: 32 rows x 64 cols
    int grp = lane >> 2, qid = lane & 3;
    int slice = blockIdx.x;
    int mbase = blockIdx.y * BM;

    // ldmatrix per-lane offsets: lt = tile index (lane>>3), lr = row in tile
    int lt = lane >> 3, lr = lane & 7;
    // A tiles: t0 = (rows +0, k+0), t1 = (rows +8, k+0), t2 = (+0, k+16), t3 = (+8, k+16)
    uint32_t offA[2];
    #pragma unroll
    for (int mi = 0; mi < 2; mi++)
        offA[mi] = (uint32_t)((warp_m*32 + mi*16 + (lt & 1)*8 + lr) * SLK + (lt >> 1) * 16);
    // B tiles (pair p covers ni=2p,2p+1): t0 = (ni, k+0), t1 = (ni, k+16),
    //                                     t2 = (ni+1, k+0), t3 = (ni+1, k+16)
    uint32_t offB[4];
    #pragma unroll
    for (int p = 0; p < 4; p++)
        offB[p] = (uint32_t)(STAGE_B + (warp_n*64 + (2*p + (lt >> 1))*8 + lr) * SLK
                             + (lt & 1) * 16);

    load_stage(0, 0, sb, mbase, slice, tid);
    asm volatile("cp.async.commit_group;\n" ::);
    load_stage(1, 1, sb, mbase, slice, tid);
    asm volatile("cp.async.commit_group;\n" ::);

    uint32_t t1[4], t2[4], t3[4];
    #pragma unroll
    for (int s4 = 0; s4 < 4; s4++) { t1[s4]=0; t2[s4]=0; t3[s4]=0; }

    float c[2][8][4];

    #pragma unroll 1
    for (int s = 0; s < NSTAGES; s++) {
        if ((s & 1) == 0) {
            #pragma unroll
            for (int mi = 0; mi < 2; mi++)
                #pragma unroll
                for (int ni = 0; ni < 8; ni++)
                    #pragma unroll
                    for (int j = 0; j < 4; j++) c[mi][ni][j] = 0.0f;
        }
        if (s < NSTAGES - 2) asm volatile("cp.async.wait_group 1;\n" ::);
        else                 asm volatile("cp.async.wait_group 0;\n" ::);
        __syncthreads();
        if (s + 2 < NSTAGES) {
            load_stage(s + 2, (s + 2) % 3, sb, mbase, slice, tid);
            asm volatile("cp.async.commit_group;\n" ::);
        }

        uint32_t base = sb + (uint32_t)(s % 3) * STAGE_BYTES;
        #pragma unroll
        for (int ks = 0; ks < 4; ks++) {
            uint32_t ksb = ks * 32;
            uint32_t a[2][4], b[8][2];
            #pragma unroll
            for (int mi = 0; mi < 2; mi++)
                LDMATRIX_X4(a[mi][0], a[mi][1], a[mi][2], a[mi][3],
                            base + offA[mi] + ksb);
            #pragma unroll
            for (int p = 0; p < 4; p++)
                LDMATRIX_X4(b[2*p][0], b[2*p][1], b[2*p+1][0], b[2*p+1][1],
                            base + offB[p] + ksb);
            #pragma unroll
            for (int mi = 0; mi < 2; mi++)
                #pragma unroll
                for (int ni = 0; ni < 8; ni++)
                    asm volatile(
                        "mma.sync.aligned.m16n8k32.row.col.f32.e4m3.e4m3.f32 "
                        "{%0,%1,%2,%3}, {%4,%5,%6,%7}, {%8,%9}, {%0,%1,%2,%3};\n"
                        : "+f"(c[mi][ni][0]), "+f"(c[mi][ni][1]),
                          "+f"(c[mi][ni][2]), "+f"(c[mi][ni][3])
                        : "r"(a[mi][0]), "r"(a[mi][1]), "r"(a[mi][2]), "r"(a[mi][3]),
                          "r"(b[ni][0]), "r"(b[ni][1]));
        }

        if (s & 1) {   // chunk kc = s>>1 complete: update packed top-3
            int kc = s >> 1;
            #pragma unroll
            for (int s4 = 0; s4 < 4; s4++) {
                int mi = s4 >> 1, h = s4 & 1;
                float m0 = -1e30f;
                #pragma unroll
                for (int ni = 0; ni < 8; ni++)
                    m0 = fmaxf(m0, fmaxf(c[mi][ni][h*2], c[mi][ni][h*2+1]));
                if ((__float_as_uint(m0 + 512.0f) | 0x1FFu) >= t3[s4]) {
                    #pragma unroll
                    for (int ni = 0; ni < 8; ni++)
                        #pragma unroll
                        for (int j = 0; j < 2; j++) {
                            float v = c[mi][ni][h*2 + j];
                            uint32_t col = kc*128 + warp_n*64 + ni*8 + qid*2 + j;
                            uint32_t u = (__float_as_uint(v + 512.0f) & 0xFFFFFE00u)
                                       | (511u - col);
                            if (u > t1[s4])      { t3[s4]=t2[s4]; t2[s4]=t1[s4]; t1[s4]=u; }
                            else if (u > t2[s4]) { t3[s4]=t2[s4]; t2[s4]=u; }
                            else if (u > t3[s4]) { t3[s4]=u; }
                        }
                }
            }
        }
    }

    // intra-CTA merge: per row, 8 threads x top-3 keys -> slice top-3
    __syncthreads();
    uint32_t* mk = (uint32_t*)sm;      // [128][24]
    #pragma unroll
    for (int s4 = 0; s4 < 4; s4++) {
        int row = warp_m*32 + (s4>>1)*16 + (s4&1)*8 + grp;
        int base2 = row * 24 + (warp_n*4 + qid) * 3;
        mk[base2+0] = t1[s4]; mk[base2+1] = t2[s4]; mk[base2+2] = t3[s4];
    }
    __syncthreads();
    if (tid < 128) {
        uint32_t b1=0, b2=0, b3=0;
        #pragma unroll
        for (int s2 = 0; s2 < 24; s2++) {
            uint32_t u = mk[tid*24 + s2];
            if (u > b1)      { b3=b2; b2=b1; b1=u; }
            else if (u > b2) { b3=b2; b2=u; }
            else if (u > b3) { b3=u; }
        }
        int n = mbase + tid;
        int base2 = n * NCAND + slice * 3;
        uint32_t ks_[3] = {b1, b2, b3};
        #pragma unroll
        for (int j = 0; j < 3; j++) {
            uint32_t u = ks_[j];
            g_candv[base2+j] = (__uint_as_float(u & 0xFFFFFE00u) - 512.0f) * (1.0f/256.0f);
            g_candi[base2+j] = slice * CPS + (int)(511u - (u & 0x1FFu));
        }
    }
}

// ------------------------------------------------------------------
// fused: margin rescue over 48 candidates (exact fp32) -> rotation
// -> commit loss -> transposed write.  block = 32 tokens, warp = 4 tokens.
__global__ void rotate_out_kernel(float* __restrict__ out) {
    __shared__ float tile[256][33];
    int b = blockIdx.y, l0 = blockIdx.x * 32;
    int tid = threadIdx.x, wid = tid >> 5, lane = tid & 31;

    #pragma unroll
    for (int i = 0; i < 4; i++) {
        int t = wid * 4 + i;
        int n = b * LL + l0 + t;

        float va = g_candv[n*NCAND + lane];
        int   ka = g_candi[n*NCAND + lane];
        float vb = (lane < 16) ? g_candv[n*NCAND + 32 + lane] : -3.0f;
        int   kb = (lane < 16) ? g_candi[n*NCAND + 32 + lane] : 0x7fffffff;
        float rmax = fmaxf(va, vb);
        #pragma unroll
        for (int o = 16; o; o >>= 1) rmax = fmaxf(rmax, __shfl_xor_sync(~0u, rmax, o));
        float thr = rmax - MARGIN;

        const float4* xp = (const float4*)(g_xn + (size_t)n * DD);
        float4 xa0 = xp[lane*2], xa1 = xp[lane*2 + 1];
        float bestv = -3.0f; int besti = 0x7fffffff;
        for (int ci = 0; ci < NCAND; ci++) {
            float v; int k;
            if (ci < 32) { v = __shfl_sync(~0u, va, ci);      k = __shfl_sync(~0u, ka, ci); }
            else         { v = __shfl_sync(~0u, vb, ci - 32); k = __shfl_sync(~0u, kb, ci - 32); }
            if (v >= thr) {
                const float4* cp = (const float4*)(g_cbn + (size_t)k * DD);
                float4 c0 = cp[lane*2], c1 = cp[lane*2 + 1];
                float d = xa0.x*c0.x + xa0.y*c0.y + xa0.z*c0.z + xa0.w*c0.w
                        + xa1.x*c1.x + xa1.y*c1.y + xa1.z*c1.z + xa1.w*c1.w;
                #pragma unroll
                for (int o = 16; o; o >>= 1) d += __shfl_xor_sync(~0u, d, o);
                if (d > bestv || (d == bestv && k < besti)) { bestv = d; besti = k; }
            }
        }

        float nrm = g_norm[n];
        const float4* qp = (const float4*)(g_cbn + (size_t)besti * DD);
        float4 x0 = xp[lane], x1 = xp[lane + 32];
        float4 q0 = qp[lane], q1 = qp[lane + 32];
        float s0x = x0.x + q0.x, s0y = x0.y + q0.y, s0z = x0.z + q0.z, s0w = x0.w + q0.w;
        float s1x = x1.x + q1.x, s1y = x1.y + q1.y, s1z = x1.z + q1.z, s1w = x1.w + q1.w;
        float ss = s0x*s0x + s0y*s0y + s0z*s0z + s0w*s0w
                 + s1x*s1x + s1y*s1y + s1z*s1z + s1w*s1w;
        float xs = x0.x*s0x + x0.y*s0y + x0.z*s0z + x0.w*s0w
                 + x1.x*s1x + x1.y*s1y + x1.z*s1z + x1.w*s1w;
        #pragma unroll
        for (int o = 16; o; o >>= 1) {
            ss += __shfl_xor_sync(~0u, ss, o);
            xs += __shfl_xor_sync(~0u, xs, o);
        }
        float sn = fmaxf(sqrtf(ss), EPSF);
        float cc = 2.0f * (xs / sn) / sn;

        float4 r0, r1;
        r0.x = x0.x - cc*s0x + 2.0f*q0.x;  r0.y = x0.y - cc*s0y + 2.0f*q0.y;
        r0.z = x0.z - cc*s0z + 2.0f*q0.z;  r0.w = x0.w - cc*s0w + 2.0f*q0.w;
        r1.x = x1.x - cc*s1x + 2.0f*q1.x;  r1.y = x1.y - cc*s1y + 2.0f*q1.y;
        r1.z = x1.z - cc*s1z + 2.0f*q1.z;  r1.w = x1.w - cc*s1w + 2.0f*q1.w;

        int d0 = lane * 4;
        tile[d0+0][t] = r0.x; tile[d0+1][t] = r0.y; tile[d0+2][t] = r0.z; tile[d0+3][t] = r0.w;
        tile[128+d0+0][t] = r1.x; tile[128+d0+1][t] = r1.y;
        tile[128+d0+2][t] = r1.z; tile[128+d0+3][t] = r1.w;

        float d0x = r0.x - x0.x*nrm, d0y = r0.y - x0.y*nrm, d0z = r0.z - x0.z*nrm, d0w = r0.w - x0.w*nrm;
        float d1x = r1.x - x1.x*nrm, d1y = r1.y - x1.y*nrm, d1z = r1.z - x1.z*nrm, d1w = r1.w - x1.w*nrm;
        float cs = d0x*d0x + d0y*d0y + d0z*d0z + d0w*d0w
                 + d1x*d1x + d1y*d1y + d1z*d1z + d1w*d1w;
        #pragma unroll
        for (int o = 16; o; o >>= 1) cs += __shfl_xor_sync(~0u, cs, o);
        if (lane == 0) atomicAdd(&g_acc, (double)cs);
    }
    __syncthreads();

    #pragma unroll
    for (int j = 0; j < 32; j++) {
        int d = wid * 32 + j;
        out[(size_t)b * DD * LL + (size_t)d * LL + l0 + lane] = tile[d][lane];
    }
}

__global__ void finalize_kernel(float* __restrict__ out, int out_size) {
    long q = (long)BB * DD * LL;
    float loss = (float)(0.25 * g_acc / (double)((long)NN * DD));
    for (long i = q + threadIdx.x; i < (long)out_size; i += blockDim.x) out[i] = loss;
}

// ------------------------------------------------------------------
extern "C" void kernel_launch(void* const* d_in, const int* in_sizes, int n_in,
                              void* d_out, int out_size) {
    const float* x  = (const float*)d_in[0];   // [4,256,4096]
    const float* cb = (const float*)d_in[1];   // [8192,256]
    float* out = (float*)d_out;

    static int attr_set = 0;
    if (!attr_set) {
        cudaFuncSetAttribute(gemm_topk_kernel,
                             cudaFuncAttributeMaxDynamicSharedMemorySize, GSMEM);
        attr_set = 1;
    }

    init_acc_kernel<<<1, 1>>>();
    normalize_codebook_kernel<<<KK / 8, 256>>>(cb);
    make_xn_kernel<<<dim3(LL / 32, BB), 256>>>(x);
    gemm_topk_kernel<<<dim3(KSPLIT, NN / BM), 256, GSMEM>>>();
    rotate_out_kernel<<<dim3(LL / 32, BB), 256>>>(out);
    finalize_kernel<<<1, 256>>>(out, out_size);
}

// round 9
// speedup vs baseline: 2.1491x; 1.0888x over previous
#include <cuda_runtime.h>
#include <cuda_bf16.h>
#include <math.h>
#include <stdint.h>

#define BB 4
#define DD 256
#define LL 4096
#define NN (BB*LL)      // 16384 tokens
#define KK 8192
#define EPSF 1e-12f
#define MARGIN 0.03f          // fp8 rescue margin (unscaled sims)
#define F8SCALE 16.0f         // per-side scale -> dots scaled by 256

#define KSPLIT 16
#define CPS (KK/KSPLIT)        // 512 codes per slice
#define NCAND (KSPLIT*3)       // 48 candidates per token

// ---- GEMM tiling ----
#define BM 128
#define BN 128
#define SLK 144                 // smem row stride bytes (conflict-free)
#define STAGE 18432             // 128 rows x 144 B (one operand, one k-half)
#define SA_BYTES (2*STAGE)      // A resident: both k-halves
#define SB_OFF SA_BYTES         // B ring base
#define NSTAGES 8               // 4 chunks x 2 k-halves
#define GSMEM (SA_BYTES + 3*STAGE)   // 92160

// ---- device scratch ----
__device__ float    g_cbn[KK*DD];     // normalized codebook fp32 (8 MB)
__device__ float    g_xn[NN*DD];      // normalized tokens fp32 (16 MB)
__device__ uint8_t  g_c8[KK*DD];      // fp8 e4m3 codebook *16 (2 MB)
__device__ uint8_t  g_x8[NN*DD];      // fp8 e4m3 tokens *16 (4 MB)
__device__ float    g_norm[NN];
__device__ float    g_candv[NN*NCAND];
__device__ int      g_candi[NN*NCAND];
__device__ double   g_acc;

// ------------------------------------------------------------------
// result: low byte = e4m3(lo), high byte = e4m3(hi)
__device__ __forceinline__ uint16_t pack_e4m3x2(float lo, float hi) {
    uint16_t r;
    asm("cvt.rn.satfinite.e4m3x2.f32 %0, %1, %2;" : "=h"(r) : "f"(hi), "f"(lo));
    return r;
}

#define LDMATRIX_X4(r0, r1, r2, r3, addr) \
    asm volatile("ldmatrix.sync.aligned.m8n8.x4.shared.b16 {%0,%1,%2,%3}, [%4];" \
        : "=r"(r0), "=r"(r1), "=r"(r2), "=r"(r3) : "r"(addr))

// one warp per codebook row: cn = c / max(||c||, eps); fp32 + fp8 outputs.
// also zeroes g_acc (block 0 thread 0).
__global__ void normalize_codebook_kernel(const float* __restrict__ cb) {
    if (blockIdx.x == 0 && threadIdx.x == 0) g_acc = 0.0;
    int row  = blockIdx.x * 8 + (threadIdx.x >> 5);
    int lane = threadIdx.x & 31;
    const float4* src = (const float4*)(cb + (size_t)row * DD);
    float4 v0 = src[lane];
    float4 v1 = src[lane + 32];
    float ss = v0.x*v0.x + v0.y*v0.y + v0.z*v0.z + v0.w*v0.w
             + v1.x*v1.x + v1.y*v1.y + v1.z*v1.z + v1.w*v1.w;
    #pragma unroll
    for (int o = 16; o; o >>= 1) ss += __shfl_xor_sync(~0u, ss, o);
    float inv = 1.0f / fmaxf(sqrtf(ss), EPSF);
    v0.x*=inv; v0.y*=inv; v0.z*=inv; v0.w*=inv;
    v1.x*=inv; v1.y*=inv; v1.z*=inv; v1.w*=inv;
    float4* dst = (float4*)(g_cbn + (size_t)row * DD);
    dst[lane] = v0; dst[lane + 32] = v1;
    uint32_t u0 = (uint32_t)pack_e4m3x2(v0.x*F8SCALE, v0.y*F8SCALE)
                | ((uint32_t)pack_e4m3x2(v0.z*F8SCALE, v0.w*F8SCALE) << 16);
    uint32_t u1 = (uint32_t)pack_e4m3x2(v1.x*F8SCALE, v1.y*F8SCALE)
                | ((uint32_t)pack_e4m3x2(v1.z*F8SCALE, v1.w*F8SCALE) << 16);
    uint32_t* h8 = (uint32_t*)(g_c8 + (size_t)row * DD);
    h8[lane] = u0; h8[lane + 32] = u1;
}

// fused: transpose [B,D,L] tile -> norms -> xn fp32 + fp8 (single x read)
__global__ void make_xn_kernel(const float* __restrict__ x) {
    __shared__ float tile[32][261];
    int b = blockIdx.y, l0 = blockIdx.x * 32;
    int tid = threadIdx.x, wid = tid >> 5, lane = tid & 31;
    #pragma unroll
    for (int j = 0; j < 32; j++) {
        int d = wid * 32 + j;
        tile[lane][d] = x[(size_t)b * DD * LL + (size_t)d * LL + l0 + lane];
    }
    __syncthreads();
    #pragma unroll
    for (int i = 0; i < 4; i++) {
        int t = wid * 4 + i;
        int n = b * LL + l0 + t;
        float ss = 0.0f;
        #pragma unroll
        for (int j = 0; j < 8; j++) { float v = tile[t][lane + 32*j]; ss = fmaf(v, v, ss); }
        #pragma unroll
        for (int o = 16; o; o >>= 1) ss += __shfl_xor_sync(~0u, ss, o);
        float nrm = fmaxf(sqrtf(ss), EPSF);
        float inv = 1.0f / nrm;
        if (lane == 0) g_norm[n] = nrm;
        #pragma unroll
        for (int j = 0; j < 8; j++) {
            int d = lane + 32*j;
            float v = tile[t][d] * inv;
            g_xn[(size_t)n * DD + d] = v;
            g_x8[(size_t)n * DD + d] = (uint8_t)(pack_e4m3x2(v*F8SCALE, 0.0f) & 0xFF);
        }
    }
}

// ------------------------------------------------------------------
#define CP_ASYNC16(dst, src) \
    asm volatile("cp.async.cg.shared.global [%0], [%1], 16;\n" :: "r"(dst), "l"(src))

// A: both k-halves, loaded once (8 cp.async per thread)
__device__ __forceinline__ void load_A(uint32_t sb, int mbase, int tid) {
    #pragma unroll
    for (int h = 0; h < 2; h++)
        #pragma unroll
        for (int i = 0; i < 4; i++) {
            int idx = tid + i * 256;
            int row = idx >> 3, c = (idx & 7) * 16;
            CP_ASYNC16(sb + h * STAGE + row * SLK + c,
                       g_x8 + (size_t)(mbase + row) * DD + h * 128 + c);
        }
}

// B stage s -> ring slot r (4 cp.async per thread)
__device__ __forceinline__ void load_B(int s, int r, uint32_t sb,
                                       int slice, int tid) {
    int kb = (s & 1) * 128;
    int kc = s >> 1;
    const uint8_t* src = g_c8 + (size_t)(slice * CPS + kc * BN) * DD + kb;
    uint32_t dst = sb + SB_OFF + r * STAGE;
    #pragma unroll
    for (int i = 0; i < 4; i++) {
        int idx = tid + i * 256;
        int row = idx >> 3, c = (idx & 7) * 16;
        CP_ASYNC16(dst + row * SLK + c, src + (size_t)row * DD + c);
    }
}

// fused fp8 mma GEMM + per-(token,slice) packed top-3; ldmatrix feed.
// A resident in smem; B 3-slot ring. grid = (KSPLIT, NN/BM).
__global__ void __launch_bounds__(256, 2) gemm_topk_kernel() {
    extern __shared__ uint8_t sm[];
    uint32_t sb = (uint32_t)__cvta_generic_to_shared(sm);
    int tid = threadIdx.x;
    int wid = tid >> 5, lane = tid & 31;
    int warp_m = wid & 3, warp_n = wid >> 2;     // 4x2 warps: 32 rows x 64 cols
    int grp = lane >> 2, qid = lane & 3;
    int slice = blockIdx.x;
    int mbase = blockIdx.y * BM;

    // ldmatrix per-lane offsets: lt = tile index (lane>>3), lr = row in tile
    int lt = lane >> 3, lr = lane & 7;
    uint32_t offA[2];
    #pragma unroll
    for (int mi = 0; mi < 2; mi++)
        offA[mi] = (uint32_t)((warp_m*32 + mi*16 + (lt & 1)*8 + lr) * SLK + (lt >> 1) * 16);
    uint32_t offB[4];
    #pragma unroll
    for (int p = 0; p < 4; p++)
        offB[p] = (uint32_t)((warp_n*64 + (2*p + (lt >> 1))*8 + lr) * SLK + (lt & 1) * 16);

    // prologue: A (both halves) + B0 as group0; B1 as group1
    load_A(sb, mbase, tid);
    load_B(0, 0, sb, slice, tid);
    asm volatile("cp.async.commit_group;\n" ::);
    load_B(1, 1, sb, slice, tid);
    asm volatile("cp.async.commit_group;\n" ::);

    uint32_t t1[4], t2[4], t3[4];
    #pragma unroll
    for (int s4 = 0; s4 < 4; s4++) { t1[s4]=0; t2[s4]=0; t3[s4]=0; }

    float c[2][8][4];

    #pragma unroll 1
    for (int s = 0; s < NSTAGES; s++) {
        if ((s & 1) == 0) {
            #pragma unroll
            for (int mi = 0; mi < 2; mi++)
                #pragma unroll
                for (int ni = 0; ni < 8; ni++)
                    #pragma unroll
                    for (int j = 0; j < 4; j++) c[mi][ni][j] = 0.0f;
        }
        if (s < NSTAGES - 2) asm volatile("cp.async.wait_group 1;\n" ::);
        else                 asm volatile("cp.async.wait_group 0;\n" ::);
        __syncthreads();
        if (s + 2 < NSTAGES) {
            load_B(s + 2, (s + 2) % 3, sb, slice, tid);
            asm volatile("cp.async.commit_group;\n" ::);
        }

        uint32_t a_base = sb + (uint32_t)(s & 1) * STAGE;
        uint32_t b_base = sb + SB_OFF + (uint32_t)(s % 3) * STAGE;
        #pragma unroll
        for (int ks = 0; ks < 4; ks++) {
            uint32_t ksb = ks * 32;
            uint32_t a[2][4], b[8][2];
            #pragma unroll
            for (int mi = 0; mi < 2; mi++)
                LDMATRIX_X4(a[mi][0], a[mi][1], a[mi][2], a[mi][3],
                            a_base + offA[mi] + ksb);
            #pragma unroll
            for (int p = 0; p < 4; p++)
                LDMATRIX_X4(b[2*p][0], b[2*p][1], b[2*p+1][0], b[2*p+1][1],
                            b_base + offB[p] + ksb);
            #pragma unroll
            for (int mi = 0; mi < 2; mi++)
                #pragma unroll
                for (int ni = 0; ni < 8; ni++)
                    asm volatile(
                        "mma.sync.aligned.m16n8k32.row.col.f32.e4m3.e4m3.f32 "
                        "{%0,%1,%2,%3}, {%4,%5,%6,%7}, {%8,%9}, {%0,%1,%2,%3};\n"
                        : "+f"(c[mi][ni][0]), "+f"(c[mi][ni][1]),
                          "+f"(c[mi][ni][2]), "+f"(c[mi][ni][3])
                        : "r"(a[mi][0]), "r"(a[mi][1]), "r"(a[mi][2]), "r"(a[mi][3]),
                          "r"(b[ni][0]), "r"(b[ni][1]));
        }

        if (s & 1) {   // chunk kc = s>>1 complete: update packed top-3
            int kc = s >> 1;
            #pragma unroll
            for (int s4 = 0; s4 < 4; s4++) {
                int mi = s4 >> 1, h = s4 & 1;
                float m0 = -1e30f;
                #pragma unroll
                for (int ni = 0; ni < 8; ni++)
                    m0 = fmaxf(m0, fmaxf(c[mi][ni][h*2], c[mi][ni][h*2+1]));
                if ((__float_as_uint(m0 + 512.0f) | 0x1FFu) >= t3[s4]) {
                    #pragma unroll
                    for (int ni = 0; ni < 8; ni++)
                        #pragma unroll
                        for (int j = 0; j < 2; j++) {
                            float v = c[mi][ni][h*2 + j];
                            uint32_t col = kc*128 + warp_n*64 + ni*8 + qid*2 + j;
                            uint32_t u = (__float_as_uint(v + 512.0f) & 0xFFFFFE00u)
                                       | (511u - col);
                            if (u > t1[s4])      { t3[s4]=t2[s4]; t2[s4]=t1[s4]; t1[s4]=u; }
                            else if (u > t2[s4]) { t3[s4]=t2[s4]; t2[s4]=u; }
                            else if (u > t3[s4]) { t3[s4]=u; }
                        }
                }
            }
        }
    }

    // intra-CTA merge: per row, 8 threads x top-3 keys -> slice top-3
    __syncthreads();
    uint32_t* mk = (uint32_t*)sm;      // [128][24]
    #pragma unroll
    for (int s4 = 0; s4 < 4; s4++) {
        int row = warp_m*32 + (s4>>1)*16 + (s4&1)*8 + grp;
        int base2 = row * 24 + (warp_n*4 + qid) * 3;
        mk[base2+0] = t1[s4]; mk[base2+1] = t2[s4]; mk[base2+2] = t3[s4];
    }
    __syncthreads();
    if (tid < 128) {
        uint32_t b1=0, b2=0, b3=0;
        #pragma unroll
        for (int s2 = 0; s2 < 24; s2++) {
            uint32_t u = mk[tid*24 + s2];
            if (u > b1)      { b3=b2; b2=b1; b1=u; }
            else if (u > b2) { b3=b2; b2=u; }
            else if (u > b3) { b3=u; }
        }
        int n = mbase + tid;
        int base2 = n * NCAND + slice * 3;
        uint32_t ks_[3] = {b1, b2, b3};
        #pragma unroll
        for (int j = 0; j < 3; j++) {
            uint32_t u = ks_[j];
            g_candv[base2+j] = (__uint_as_float(u & 0xFFFFFE00u) - 512.0f) * (1.0f/256.0f);
            g_candi[base2+j] = slice * CPS + (int)(511u - (u & 0x1FFu));
        }
    }
}

// ------------------------------------------------------------------
// fused: margin rescue over 48 candidates (exact fp32) -> rotation
// -> commit loss -> transposed write.  block = 32 tokens, warp = 4 tokens.
__global__ void rotate_out_kernel(float* __restrict__ out) {
    __shared__ float tile[256][33];
    int b = blockIdx.y, l0 = blockIdx.x * 32;
    int tid = threadIdx.x, wid = tid >> 5, lane = tid & 31;

    #pragma unroll
    for (int i = 0; i < 4; i++) {
        int t = wid * 4 + i;
        int n = b * LL + l0 + t;

        float va = g_candv[n*NCAND + lane];
        int   ka = g_candi[n*NCAND + lane];
        float vb = (lane < 16) ? g_candv[n*NCAND + 32 + lane] : -3.0f;
        int   kb = (lane < 16) ? g_candi[n*NCAND + 32 + lane] : 0x7fffffff;
        float rmax = fmaxf(va, vb);
        #pragma unroll
        for (int o = 16; o; o >>= 1) rmax = fmaxf(rmax, __shfl_xor_sync(~0u, rmax, o));
        float thr = rmax - MARGIN;

        const float4* xp = (const float4*)(g_xn + (size_t)n * DD);
        float4 xa0 = xp[lane*2], xa1 = xp[lane*2 + 1];
        float bestv = -3.0f; int besti = 0x7fffffff;
        for (int ci = 0; ci < NCAND; ci++) {
            float v; int k;
            if (ci < 32) { v = __shfl_sync(~0u, va, ci);      k = __shfl_sync(~0u, ka, ci); }
            else         { v = __shfl_sync(~0u, vb, ci - 32); k = __shfl_sync(~0u, kb, ci - 32); }
            if (v >= thr) {
                const float4* cp = (const float4*)(g_cbn + (size_t)k * DD);
                float4 c0 = cp[lane*2], c1 = cp[lane*2 + 1];
                float d = xa0.x*c0.x + xa0.y*c0.y + xa0.z*c0.z + xa0.w*c0.w
                        + xa1.x*c1.x + xa1.y*c1.y + xa1.z*c1.z + xa1.w*c1.w;
                #pragma unroll
                for (int o = 16; o; o >>= 1) d += __shfl_xor_sync(~0u, d, o);
                if (d > bestv || (d == bestv && k < besti)) { bestv = d; besti = k; }
            }
        }

        float nrm = g_norm[n];
        const float4* qp = (const float4*)(g_cbn + (size_t)besti * DD);
        float4 x0 = xp[lane], x1 = xp[lane + 32];
        float4 q0 = qp[lane], q1 = qp[lane + 32];
        float s0x = x0.x + q0.x, s0y = x0.y + q0.y, s0z = x0.z + q0.z, s0w = x0.w + q0.w;
        float s1x = x1.x + q1.x, s1y = x1.y + q1.y, s1z = x1.z + q1.z, s1w = x1.w + q1.w;
        float ss = s0x*s0x + s0y*s0y + s0z*s0z + s0w*s0w
                 + s1x*s1x + s1y*s1y + s1z*s1z + s1w*s1w;
        float xs = x0.x*s0x + x0.y*s0y + x0.z*s0z + x0.w*s0w
                 + x1.x*s1x + x1.y*s1y + x1.z*s1z + x1.w*s1w;
        #pragma unroll
        for (int o = 16; o; o >>= 1) {
            ss += __shfl_xor_sync(~0u, ss, o);
            xs += __shfl_xor_sync(~0u, xs, o);
        }
        float sn = fmaxf(sqrtf(ss), EPSF);
        float cc = 2.0f * (xs / sn) / sn;

        float4 r0, r1;
        r0.x = x0.x - cc*s0x + 2.0f*q0.x;  r0.y = x0.y - cc*s0y + 2.0f*q0.y;
        r0.z = x0.z - cc*s0z + 2.0f*q0.z;  r0.w = x0.w - cc*s0w + 2.0f*q0.w;
        r1.x = x1.x - cc*s1x + 2.0f*q1.x;  r1.y = x1.y - cc*s1y + 2.0f*q1.y;
        r1.z = x1.z - cc*s1z + 2.0f*q1.z;  r1.w = x1.w - cc*s1w + 2.0f*q1.w;

        int d0 = lane * 4;
        tile[d0+0][t] = r0.x; tile[d0+1][t] = r0.y; tile[d0+2][t] = r0.z; tile[d0+3][t] = r0.w;
        tile[128+d0+0][t] = r1.x; tile[128+d0+1][t] = r1.y;
        tile[128+d0+2][t] = r1.z; tile[128+d0+3][t] = r1.w;

        float d0x = r0.x - x0.x*nrm, d0y = r0.y - x0.y*nrm, d0z = r0.z - x0.z*nrm, d0w = r0.w - x0.w*nrm;
        float d1x = r1.x - x1.x*nrm, d1y = r1.y - x1.y*nrm, d1z = r1.z - x1.z*nrm, d1w = r1.w - x1.w*nrm;
        float cs = d0x*d0x + d0y*d0y + d0z*d0z + d0w*d0w
                 + d1x*d1x + d1y*d1y + d1z*d1z + d1w*d1w;
        #pragma unroll
        for (int o = 16; o; o >>= 1) cs += __shfl_xor_sync(~0u, cs, o);
        if (lane == 0) atomicAdd(&g_acc, (double)cs);
    }
    __syncthreads();

    #pragma unroll
    for (int j = 0; j < 32; j++) {
        int d = wid * 32 + j;
        out[(size_t)b * DD * LL + (size_t)d * LL + l0 + lane] = tile[d][lane];
    }
}

__global__ void finalize_kernel(float* __restrict__ out, int out_size) {
    long q = (long)BB * DD * LL;
    float loss = (float)(0.25 * g_acc / (double)((long)NN * DD));
    for (long i = q + threadIdx.x; i < (long)out_size; i += blockDim.x) out[i] = loss;
}

// ------------------------------------------------------------------
extern "C" void kernel_launch(void* const* d_in, const int* in_sizes, int n_in,
                              void* d_out, int out_size) {
    const float* x  = (const float*)d_in[0];   // [4,256,4096]
    const float* cb = (const float*)d_in[1];   // [8192,256]
    float* out = (float*)d_out;

    static int attr_set = 0;
    if (!attr_set) {
        cudaFuncSetAttribute(gemm_topk_kernel,
                             cudaFuncAttributeMaxDynamicSharedMemorySize, GSMEM);
        attr_set = 1;
    }

    normalize_codebook_kernel<<<KK / 8, 256>>>(cb);
    make_xn_kernel<<<dim3(LL / 32, BB), 256>>>(x);
    gemm_topk_kernel<<<dim3(KSPLIT, NN / BM), 256, GSMEM>>>();
    rotate_out_kernel<<<dim3(LL / 32, BB), 256>>>(out);
    finalize_kernel<<<1, 256>>>(out, out_size);
}